// round 1
// baseline (speedup 1.0000x reference)
#include <cuda_runtime.h>
#include <cstdint>

// Problem constants (fixed by the dataset problem).
#define NSLICE 32      // B*KI = 8*4
#define NN     2048    // nodes per slice
#define IW     32
#define OW     32

// exp(-sq/2) = exp2f(C1 * sq), C1 = -1/(2 ln 2)
#define C1   (-0.7213475204444817f)
#define M2C1 ( 1.4426950408889634f)   // -2*C1

// Scratch (device globals: allocation-free contract).
__device__ float g_inv_d2[NSLICE * NN];          // 1/degree^2 per node
__device__ float g_wl[(size_t)NSLICE * NN * OW]; // (w/d^2) @ lin_w^T

// ---------------------------------------------------------------------------
// fp32x2 packed FMA helpers (Blackwell sm_100+)
// ---------------------------------------------------------------------------
__device__ __forceinline__ unsigned long long fma_f32x2(
    unsigned long long a, unsigned long long b, unsigned long long c) {
    unsigned long long d;
    asm("fma.rn.f32x2 %0, %1, %2, %3;" : "=l"(d) : "l"(a), "l"(b), "l"(c));
    return d;
}
__device__ __forceinline__ unsigned long long pack_dup_f32(float x) {
    unsigned long long d;
    asm("mov.b64 %0, {%1, %1};" : "=l"(d) : "f"(x));
    return d;
}
__device__ __forceinline__ void unpack_f32x2(unsigned long long v, float& lo, float& hi) {
    asm("mov.b64 {%0, %1}, %2;" : "=f"(lo), "=f"(hi) : "l"(v));
}

// ---------------------------------------------------------------------------
// Pass A: degrees.  inv_d2[i] = 1 / (sum_j exp(-||pi-pj||^2/2))^2
// grid = NSLICE*16 blocks, 128 threads; each block: 128 rows of one slice.
// ---------------------------------------------------------------------------
__global__ void __launch_bounds__(128) deg_kernel(
    const float* __restrict__ pos, float* __restrict__ inv_d2) {
    __shared__ float4 ps[NN];   // (x, y, z, C1*|p|^2)  32 KB

    int slice = blockIdx.x >> 4;
    int rblk  = blockIdx.x & 15;
    const float* p = pos + (size_t)slice * NN * 3;

    for (int n = threadIdx.x; n < NN; n += 128) {
        float x = p[3 * n + 0], y = p[3 * n + 1], z = p[3 * n + 2];
        ps[n] = make_float4(x, y, z, C1 * (x * x + y * y + z * z));
    }
    __syncthreads();

    int i = rblk * 128 + threadIdx.x;
    float4 pi = ps[i];
    float qx = M2C1 * pi.x, qy = M2C1 * pi.y, qz = M2C1 * pi.z;
    float csi = pi.w;

    float acc = 0.0f;
#pragma unroll 8
    for (int j = 0; j < NN; j++) {
        float4 pj = ps[j];
        float t = csi + pj.w;
        t = fmaf(qx, pj.x, t);
        t = fmaf(qy, pj.y, t);
        t = fmaf(qz, pj.z, t);
        acc += exp2f(t);
    }
    inv_d2[slice * NN + i] = 1.0f / (acc * acc);
}

// ---------------------------------------------------------------------------
// Pass B: wl[j][o] = inv_d2[j] * sum_w w[j][w] * lin_w[o][w]
// 256 threads = 8 warps, one warp per node j.
// ---------------------------------------------------------------------------
__global__ void __launch_bounds__(256) wl_kernel(
    const float* __restrict__ w, const float* __restrict__ lin_w,
    const float* __restrict__ inv_d2, float* __restrict__ wl) {
    __shared__ float lw[OW * 33];   // padded: lw[o*33 + k]

    for (int t = threadIdx.x; t < OW * IW; t += 256)
        lw[(t >> 5) * 33 + (t & 31)] = lin_w[t];
    __syncthreads();

    int warp = threadIdx.x >> 5;
    int lane = threadIdx.x & 31;           // lane = output channel o
    long gj = (long)blockIdx.x * 8 + warp; // global node index (slice*NN + j)

    float mw = w[gj * IW + lane];
    float acc = 0.0f;
#pragma unroll
    for (int k = 0; k < IW; k++) {
        float wv = __shfl_sync(0xffffffffu, mw, k);
        acc = fmaf(wv, lw[lane * 33 + k], acc);
    }
    wl[gj * OW + lane] = acc * inv_d2[gj];
}

// ---------------------------------------------------------------------------
// Pass C (hot): out[i][o] = inv_d2[i] * sum_j exp2(C1*sq(i,j)) * wl[j][o] + b[o]
// grid = NSLICE*16 blocks, 128 threads, 1 row per thread, 32 fp32 accs as
// 16 packed f32x2 accumulators -> halves fma-pipe instruction count.
// ---------------------------------------------------------------------------
#define JT 64   // j-tile held in SMEM

__global__ void __launch_bounds__(128) main_kernel(
    const float* __restrict__ pos, const float* __restrict__ wl,
    const float* __restrict__ inv_d2, const float* __restrict__ lin_b,
    float* __restrict__ out) {
    __shared__ float4 ps[NN];         // 32 KB
    __shared__ float4 wls[JT * 8];    // JT rows x 32 floats = 8 KB

    int slice = blockIdx.x >> 4;
    int rblk  = blockIdx.x & 15;
    const float* p = pos + (size_t)slice * NN * 3;

    for (int n = threadIdx.x; n < NN; n += 128) {
        float x = p[3 * n + 0], y = p[3 * n + 1], z = p[3 * n + 2];
        ps[n] = make_float4(x, y, z, C1 * (x * x + y * y + z * z));
    }

    int i = rblk * 128 + threadIdx.x;
    const float4* wlg = (const float4*)(wl + (size_t)slice * NN * OW);

    unsigned long long acc[16];
#pragma unroll
    for (int r = 0; r < 16; r++) acc[r] = 0ULL;

    __syncthreads();            // ps ready
    float4 pi = ps[i];
    float qx = M2C1 * pi.x, qy = M2C1 * pi.y, qz = M2C1 * pi.z;
    float csi = pi.w;

    for (int j0 = 0; j0 < NN; j0 += JT) {
        // stage wl tile: JT*8 float4 = 512 float4 / 128 threads = 4 each
#pragma unroll
        for (int r = 0; r < 4; r++) {
            int idx = r * 128 + threadIdx.x;
            wls[idx] = wlg[j0 * 8 + idx];
        }
        __syncthreads();

#pragma unroll 2
        for (int jj = 0; jj < JT; jj++) {
            float4 pj = ps[j0 + jj];
            float t = csi + pj.w;
            t = fmaf(qx, pj.x, t);
            t = fmaf(qy, pj.y, t);
            t = fmaf(qz, pj.z, t);
            float e = exp2f(t);
            unsigned long long k2 = pack_dup_f32(e);
            const ulonglong2* row = (const ulonglong2*)(wls + jj * 8);
#pragma unroll
            for (int r = 0; r < 8; r++) {
                ulonglong2 v = row[r];   // LDS.128, warp-broadcast
                acc[2 * r + 0] = fma_f32x2(k2, v.x, acc[2 * r + 0]);
                acc[2 * r + 1] = fma_f32x2(k2, v.y, acc[2 * r + 1]);
            }
        }
        __syncthreads();        // protect wls before next overwrite
    }

    float invd = inv_d2[slice * NN + i];
    float* orow = out + ((size_t)slice * NN + i) * OW;
#pragma unroll
    for (int r = 0; r < 8; r++) {
        float a0, a1, a2, a3;
        unpack_f32x2(acc[2 * r + 0], a0, a1);
        unpack_f32x2(acc[2 * r + 1], a2, a3);
        float4 v;
        v.x = fmaf(a0, invd, lin_b[4 * r + 0]);
        v.y = fmaf(a1, invd, lin_b[4 * r + 1]);
        v.z = fmaf(a2, invd, lin_b[4 * r + 2]);
        v.w = fmaf(a3, invd, lin_b[4 * r + 3]);
        ((float4*)orow)[r] = v;
    }
}

// ---------------------------------------------------------------------------
// Launcher
// ---------------------------------------------------------------------------
extern "C" void kernel_launch(void* const* d_in, const int* in_sizes, int n_in,
                              void* d_out, int out_size) {
    const float* positions = (const float*)d_in[0];  // (8,4,2048,3)
    const float* weights   = (const float*)d_in[1];  // (8,4,2048,32)
    const float* lin_w     = (const float*)d_in[2];  // (32,32)
    const float* lin_b     = (const float*)d_in[3];  // (32,)
    float* out = (float*)d_out;

    int pos_elems = in_sizes[0];                     // 196608
    float* out_weights = out + pos_elems;

    float* inv_d2;
    float* wl;
    cudaGetSymbolAddress((void**)&inv_d2, g_inv_d2);
    cudaGetSymbolAddress((void**)&wl, g_wl);

    // positions passthrough (first element of the output tuple)
    cudaMemcpyAsync(out, positions, (size_t)pos_elems * sizeof(float),
                    cudaMemcpyDeviceToDevice);

    deg_kernel<<<NSLICE * 16, 128>>>(positions, inv_d2);
    wl_kernel<<<(NSLICE * NN) / 8, 256>>>(weights, lin_w, inv_d2, wl);
    main_kernel<<<NSLICE * 16, 128>>>(positions, wl, inv_d2, lin_b, out_weights);
}

// round 2
// speedup vs baseline: 2.1040x; 2.1040x over previous
#include <cuda_runtime.h>
#include <cstdint>

// Problem constants.
#define NSLICE 32      // B*KI = 8*4
#define NN     2048    // nodes per slice
#define IW     32
#define OW     32

// exp(-sq/2) = exp2(C1 * sq), C1 = -1/(2 ln 2)
#define C1   (-0.7213475204444817f)
#define M2C1 ( 1.4426950408889634f)   // -2*C1

// Scratch (device globals: allocation-free contract).
__device__ float g_inv_d2[NSLICE * NN];
// wl in B-fragment order: [slice][chunk(256)][r(8)][lane(32)], tf32-rounded.
__device__ float g_wlf[(size_t)NSLICE * NN * OW];

// ---------------------------------------------------------------------------
// PTX helpers
// ---------------------------------------------------------------------------
__device__ __forceinline__ float ex2f(float x) {
    float y; asm("ex2.approx.f32 %0, %1;" : "=f"(y) : "f"(x)); return y;
}
__device__ __forceinline__ unsigned cvt_tf32(float x) {
    unsigned y; asm("cvt.rna.tf32.f32 %0, %1;" : "=r"(y) : "f"(x)); return y;
}
__device__ __forceinline__ void mma_tf32(float* c, unsigned a0, unsigned a1,
                                         unsigned a2, unsigned a3,
                                         unsigned b0, unsigned b1) {
    asm volatile(
        "mma.sync.aligned.m16n8k8.row.col.f32.tf32.tf32.f32 "
        "{%0,%1,%2,%3}, {%4,%5,%6,%7}, {%8,%9}, {%0,%1,%2,%3};"
        : "+f"(c[0]), "+f"(c[1]), "+f"(c[2]), "+f"(c[3])
        : "r"(a0), "r"(a1), "r"(a2), "r"(a3), "r"(b0), "r"(b1));
}

// ---------------------------------------------------------------------------
// Pass A: degrees. 1024 blocks x 128 thr; 64 rows/block, 2 j-halves/row.
// ---------------------------------------------------------------------------
__global__ void __launch_bounds__(128) deg_kernel(
    const float* __restrict__ pos, float* __restrict__ inv_d2) {
    __shared__ float4 ps[NN];   // (x, y, z, C1*|p|^2)

    int slice = blockIdx.x >> 5;
    int rblk  = blockIdx.x & 31;
    const float* p = pos + (size_t)slice * NN * 3;

    for (int n = threadIdx.x; n < NN; n += 128) {
        float x = p[3 * n + 0], y = p[3 * n + 1], z = p[3 * n + 2];
        ps[n] = make_float4(x, y, z, C1 * (x * x + y * y + z * z));
    }
    __syncthreads();

    int i    = rblk * 64 + (threadIdx.x >> 1);
    int half = threadIdx.x & 1;
    float4 pi = ps[i];
    float qx = M2C1 * pi.x, qy = M2C1 * pi.y, qz = M2C1 * pi.z;
    float csi = pi.w;

    float acc = 0.0f;
    int j0 = half * (NN / 2);
#pragma unroll 8
    for (int j = j0; j < j0 + NN / 2; j++) {
        float4 pj = ps[j];
        float t = csi + pj.w;
        t = fmaf(qx, pj.x, t);
        t = fmaf(qy, pj.y, t);
        t = fmaf(qz, pj.z, t);
        acc += ex2f(t);
    }
    acc += __shfl_xor_sync(0xffffffffu, acc, 1);
    if (half == 0)
        inv_d2[slice * NN + i] = 1.0f / (acc * acc);
}

// ---------------------------------------------------------------------------
// Pass B: wl[j][o] = inv_d2[j] * (w[j,:] @ lin_w[o,:]); scatter into
// B-fragment order, tf32-rounded. One warp per node j.
// ---------------------------------------------------------------------------
__global__ void __launch_bounds__(256) wl_kernel(
    const float* __restrict__ w, const float* __restrict__ lin_w,
    const float* __restrict__ inv_d2, float* __restrict__ wlf) {
    __shared__ float lw[OW * 33];

    for (int t = threadIdx.x; t < OW * IW; t += 256)
        lw[(t >> 5) * 33 + (t & 31)] = lin_w[t];
    __syncthreads();

    int warp = threadIdx.x >> 5;
    int lane = threadIdx.x & 31;           // lane = output channel n
    long gj = (long)blockIdx.x * 8 + warp; // global node index

    float mw = w[gj * IW + lane];
    float acc = 0.0f;
#pragma unroll
    for (int k = 0; k < IW; k++) {
        float wv = __shfl_sync(0xffffffffu, mw, k);
        acc = fmaf(wv, lw[lane * 33 + k], acc);
    }
    acc *= inv_d2[gj];

    int slice = (int)(gj >> 11);
    int jl11  = (int)(gj & 2047);
    int chunk = jl11 >> 3;
    int h     = (jl11 >> 2) & 1;
    int jl    = jl11 & 3;
    int nb    = lane >> 3;
    int nl    = lane & 7;
    int r     = nb * 2 + h;
    size_t addr = ((((size_t)slice * 256 + chunk) * 8 + r) * 32) + (nl * 4 + jl);
    wlf[addr] = __uint_as_float(cvt_tf32(acc));
}

// ---------------------------------------------------------------------------
// Pass C (hot): tensor-core mainloop.
// Block = 256 thr = 8 warps; warp owns 16 rows x 32 cols; K swept in
// 8-wide chunks; A fragments (exp kernel values) generated in registers.
// ---------------------------------------------------------------------------
#define JTILE   64              // j per SMEM tile (8 chunks)
#define CHUNKS  (JTILE / 8)

__global__ void __launch_bounds__(256) main_kernel(
    const float* __restrict__ pos, const float* __restrict__ wlf,
    const float* __restrict__ inv_d2, const float* __restrict__ lin_b,
    float* __restrict__ out) {
    __shared__ float4 ps[NN];                  // 32 KB
    __shared__ float  wls[CHUNKS * 8 * 32];    // 8 KB

    int slice = blockIdx.x >> 4;
    int iblk  = blockIdx.x & 15;
    const float* p = pos + (size_t)slice * NN * 3;

    for (int n = threadIdx.x; n < NN; n += 256) {
        float x = p[3 * n + 0], y = p[3 * n + 1], z = p[3 * n + 2];
        ps[n] = make_float4(x, y, z, C1 * (x * x + y * y + z * z));
    }

    int warp = threadIdx.x >> 5;
    int lane = threadIdx.x & 31;
    int row_lo = iblk * 128 + warp * 16 + (lane >> 2);
    int row_hi = row_lo + 8;

    float acc[16];
#pragma unroll
    for (int r = 0; r < 16; r++) acc[r] = 0.0f;

    __syncthreads();
    float4 plo = ps[row_lo];
    float4 phi = ps[row_hi];
    float qxl = M2C1 * plo.x, qyl = M2C1 * plo.y, qzl = M2C1 * plo.z, csl = plo.w;
    float qxh = M2C1 * phi.x, qyh = M2C1 * phi.y, qzh = M2C1 * phi.z, csh = phi.w;

    const float* wlf_s = wlf + (size_t)slice * NN * OW;

    for (int tile = 0; tile < NN / JTILE; tile++) {
        // stage CHUNKS*8*32 floats = 512 float4 / 256 thr = 2 each
        const float4* src = (const float4*)(wlf_s + tile * (JTILE * OW));
        float4 s0 = src[threadIdx.x];
        float4 s1 = src[256 + threadIdx.x];
        __syncthreads();   // previous tile consumed
        ((float4*)wls)[threadIdx.x]       = s0;
        ((float4*)wls)[256 + threadIdx.x] = s1;
        __syncthreads();   // tile ready

#pragma unroll
        for (int c = 0; c < CHUNKS; c++) {
            int j = tile * JTILE + c * 8 + (lane & 3);
            float4 pjl = ps[j];
            float4 pjh = ps[j + 4];

            float t00 = csl + pjl.w;                  // (row_lo, j_lo)
            t00 = fmaf(qxl, pjl.x, t00);
            t00 = fmaf(qyl, pjl.y, t00);
            t00 = fmaf(qzl, pjl.z, t00);
            float t10 = csh + pjl.w;                  // (row_hi, j_lo)
            t10 = fmaf(qxh, pjl.x, t10);
            t10 = fmaf(qyh, pjl.y, t10);
            t10 = fmaf(qzh, pjl.z, t10);
            float t01 = csl + pjh.w;                  // (row_lo, j_hi)
            t01 = fmaf(qxl, pjh.x, t01);
            t01 = fmaf(qyl, pjh.y, t01);
            t01 = fmaf(qzl, pjh.z, t01);
            float t11 = csh + pjh.w;                  // (row_hi, j_hi)
            t11 = fmaf(qxh, pjh.x, t11);
            t11 = fmaf(qyh, pjh.y, t11);
            t11 = fmaf(qzh, pjh.z, t11);

            unsigned a0 = cvt_tf32(ex2f(t00));
            unsigned a1 = cvt_tf32(ex2f(t10));
            unsigned a2 = cvt_tf32(ex2f(t01));
            unsigned a3 = cvt_tf32(ex2f(t11));

            const unsigned* bb = (const unsigned*)wls + c * 256;
#pragma unroll
            for (int nb = 0; nb < 4; nb++) {
                unsigned b0 = bb[(nb * 2 + 0) * 32 + lane];
                unsigned b1 = bb[(nb * 2 + 1) * 32 + lane];
                mma_tf32(acc + nb * 4, a0, a1, a2, a3, b0, b1);
            }
        }
    }

    float invl = inv_d2[slice * NN + row_lo];
    float invh = inv_d2[slice * NN + row_hi];
    float* orow_lo = out + ((size_t)slice * NN + row_lo) * OW;
    float* orow_hi = out + ((size_t)slice * NN + row_hi) * OW;
#pragma unroll
    for (int nb = 0; nb < 4; nb++) {
        int col = nb * 8 + (lane & 3) * 2;
        float lb0 = __ldg(lin_b + col);
        float lb1 = __ldg(lin_b + col + 1);
        float2 vlo = make_float2(fmaf(acc[nb * 4 + 0], invl, lb0),
                                 fmaf(acc[nb * 4 + 1], invl, lb1));
        float2 vhi = make_float2(fmaf(acc[nb * 4 + 2], invh, lb0),
                                 fmaf(acc[nb * 4 + 3], invh, lb1));
        *(float2*)(orow_lo + col) = vlo;
        *(float2*)(orow_hi + col) = vhi;
    }
}

// ---------------------------------------------------------------------------
// Launcher
// ---------------------------------------------------------------------------
extern "C" void kernel_launch(void* const* d_in, const int* in_sizes, int n_in,
                              void* d_out, int out_size) {
    const float* positions = (const float*)d_in[0];
    const float* weights   = (const float*)d_in[1];
    const float* lin_w     = (const float*)d_in[2];
    const float* lin_b     = (const float*)d_in[3];
    float* out = (float*)d_out;

    int pos_elems = in_sizes[0];
    float* out_weights = out + pos_elems;

    float* inv_d2;
    float* wlf;
    cudaGetSymbolAddress((void**)&inv_d2, g_inv_d2);
    cudaGetSymbolAddress((void**)&wlf, g_wlf);

    cudaMemcpyAsync(out, positions, (size_t)pos_elems * sizeof(float),
                    cudaMemcpyDeviceToDevice);

    deg_kernel<<<NSLICE * 32, 128>>>(positions, inv_d2);
    wl_kernel<<<(NSLICE * NN) / 8, 256>>>(weights, lin_w, inv_d2, wlf);
    main_kernel<<<NSLICE * 16, 256>>>(positions, wlf, inv_d2, lin_b, out_weights);
}

// round 3
// speedup vs baseline: 2.1668x; 1.0299x over previous
#include <cuda_runtime.h>
#include <cstdint>

// Problem constants.
#define NSLICE 32      // B*KI = 8*4
#define NN     2048    // nodes per slice
#define IW     32
#define OW     32

// exp(-sq/2) = exp2(C1 * sq), C1 = -1/(2 ln 2)
#define C1   (-0.7213475204444817f)
#define M2C1 ( 1.4426950408889634f)   // -2*C1

// Scratch (device globals: allocation-free contract).
__device__ float g_inv_d2[NSLICE * NN];
// wl in B-fragment order: [slice][chunk(256)][r(8)][lane(32)], tf32-rounded.
__device__ float g_wlf[(size_t)NSLICE * NN * OW];

// ---------------------------------------------------------------------------
// PTX helpers
// ---------------------------------------------------------------------------
__device__ __forceinline__ float ex2f(float x) {
    float y; asm("ex2.approx.f32 %0, %1;" : "=f"(y) : "f"(x)); return y;
}
__device__ __forceinline__ unsigned cvt_tf32(float x) {
    unsigned y; asm("cvt.rna.tf32.f32 %0, %1;" : "=r"(y) : "f"(x)); return y;
}
__device__ __forceinline__ void mma_tf32(float* c, unsigned a0, unsigned a1,
                                         unsigned a2, unsigned a3,
                                         unsigned b0, unsigned b1) {
    asm volatile(
        "mma.sync.aligned.m16n8k8.row.col.f32.tf32.tf32.f32 "
        "{%0,%1,%2,%3}, {%4,%5,%6,%7}, {%8,%9}, {%0,%1,%2,%3};"
        : "+f"(c[0]), "+f"(c[1]), "+f"(c[2]), "+f"(c[3])
        : "r"(a0), "r"(a1), "r"(a2), "r"(a3), "r"(b0), "r"(b1));
}

// ---------------------------------------------------------------------------
// Pass A: degrees via tensor-core row-sum (B = ones).
// Block = 256 thr = 8 warps; warp owns 16 rows; chunk = 8 j.
// degree_i lands in acc[0]/acc[2] directly (C[i][n] = sum_k A[i][k]).
// ---------------------------------------------------------------------------
__global__ void __launch_bounds__(256) deg_kernel(
    const float* __restrict__ pos, float* __restrict__ inv_d2) {
    __shared__ float4 ps[NN];   // (x, y, z, C1*|p|^2)  32 KB

    int slice = blockIdx.x >> 4;
    int iblk  = blockIdx.x & 15;
    const float* p = pos + (size_t)slice * NN * 3;

    for (int n = threadIdx.x; n < NN; n += 256) {
        float x = p[3 * n + 0], y = p[3 * n + 1], z = p[3 * n + 2];
        ps[n] = make_float4(x, y, z, C1 * (x * x + y * y + z * z));
    }
    __syncthreads();

    int warp = threadIdx.x >> 5;
    int lane = threadIdx.x & 31;
    int row_lo = iblk * 128 + warp * 16 + (lane >> 2);
    int row_hi = row_lo + 8;

    float4 plo = ps[row_lo];
    float4 phi = ps[row_hi];
    float qxl = M2C1 * plo.x, qyl = M2C1 * plo.y, qzl = M2C1 * plo.z, csl = plo.w;
    float qxh = M2C1 * phi.x, qyh = M2C1 * phi.y, qzh = M2C1 * phi.z, csh = phi.w;

    float acc[4] = {0.0f, 0.0f, 0.0f, 0.0f};
    const unsigned ONE = 0x3f800000u;   // 1.0f (exact in tf32)

#pragma unroll 4
    for (int c = 0; c < NN / 8; c++) {
        int j = c * 8 + (lane & 3);
        float4 pjl = ps[j];
        float4 pjh = ps[j + 4];

        float t00 = csl + pjl.w;
        t00 = fmaf(qxl, pjl.x, t00);
        t00 = fmaf(qyl, pjl.y, t00);
        t00 = fmaf(qzl, pjl.z, t00);
        float t10 = csh + pjl.w;
        t10 = fmaf(qxh, pjl.x, t10);
        t10 = fmaf(qyh, pjl.y, t10);
        t10 = fmaf(qzh, pjl.z, t10);
        float t01 = csl + pjh.w;
        t01 = fmaf(qxl, pjh.x, t01);
        t01 = fmaf(qyl, pjh.y, t01);
        t01 = fmaf(qzl, pjh.z, t01);
        float t11 = csh + pjh.w;
        t11 = fmaf(qxh, pjh.x, t11);
        t11 = fmaf(qyh, pjh.y, t11);
        t11 = fmaf(qzh, pjh.z, t11);

        unsigned a0 = cvt_tf32(ex2f(t00));
        unsigned a1 = cvt_tf32(ex2f(t10));
        unsigned a2 = cvt_tf32(ex2f(t01));
        unsigned a3 = cvt_tf32(ex2f(t11));

        mma_tf32(acc, a0, a1, a2, a3, ONE, ONE);
    }

    if ((lane & 3) == 0) {
        inv_d2[slice * NN + row_lo] = 1.0f / (acc[0] * acc[0]);
        inv_d2[slice * NN + row_hi] = 1.0f / (acc[2] * acc[2]);
    }
}

// ---------------------------------------------------------------------------
// Pass B: wl[j][o] = inv_d2[j] * (w[j,:] @ lin_w[o,:]); scatter into
// B-fragment order, tf32-rounded. One warp per node j.
// ---------------------------------------------------------------------------
__global__ void __launch_bounds__(256) wl_kernel(
    const float* __restrict__ w, const float* __restrict__ lin_w,
    const float* __restrict__ inv_d2, float* __restrict__ wlf) {
    __shared__ float lw[OW * 33];

    for (int t = threadIdx.x; t < OW * IW; t += 256)
        lw[(t >> 5) * 33 + (t & 31)] = lin_w[t];
    __syncthreads();

    int warp = threadIdx.x >> 5;
    int lane = threadIdx.x & 31;           // lane = output channel n
    long gj = (long)blockIdx.x * 8 + warp; // global node index

    float mw = w[gj * IW + lane];
    float acc = 0.0f;
#pragma unroll
    for (int k = 0; k < IW; k++) {
        float wv = __shfl_sync(0xffffffffu, mw, k);
        acc = fmaf(wv, lw[lane * 33 + k], acc);
    }
    acc *= inv_d2[gj];

    int slice = (int)(gj >> 11);
    int jl11  = (int)(gj & 2047);
    int chunk = jl11 >> 3;
    int h     = (jl11 >> 2) & 1;
    int jl    = jl11 & 3;
    int nb    = lane >> 3;
    int nl    = lane & 7;
    int r     = nb * 2 + h;
    size_t addr = ((((size_t)slice * 256 + chunk) * 8 + r) * 32) + (nl * 4 + jl);
    wlf[addr] = __uint_as_float(cvt_tf32(acc));
}

// ---------------------------------------------------------------------------
// Pass C (hot): tensor-core mainloop, double-buffered wl tiles.
// Block = 256 thr = 8 warps; warp owns 16 rows x 32 cols.
// ---------------------------------------------------------------------------
#define JTILE   64              // j per SMEM tile (8 chunks)
#define CHUNKS  (JTILE / 8)
#define NTILES  (NN / JTILE)

__global__ void __launch_bounds__(256) main_kernel(
    const float* __restrict__ pos, const float* __restrict__ wlf,
    const float* __restrict__ inv_d2, const float* __restrict__ lin_b,
    float* __restrict__ out) {
    __shared__ float4 ps[NN];                     // 32 KB
    __shared__ float  wls[2][CHUNKS * 8 * 32];    // 2 x 8 KB

    int slice = blockIdx.x >> 4;
    int iblk  = blockIdx.x & 15;
    const float* p = pos + (size_t)slice * NN * 3;

    for (int n = threadIdx.x; n < NN; n += 256) {
        float x = p[3 * n + 0], y = p[3 * n + 1], z = p[3 * n + 2];
        ps[n] = make_float4(x, y, z, C1 * (x * x + y * y + z * z));
    }

    int warp = threadIdx.x >> 5;
    int lane = threadIdx.x & 31;
    int row_lo = iblk * 128 + warp * 16 + (lane >> 2);
    int row_hi = row_lo + 8;

    float acc[16];
#pragma unroll
    for (int r = 0; r < 16; r++) acc[r] = 0.0f;

    const float* wlf_s = wlf + (size_t)slice * NN * OW;

    // prologue: stage tile 0 into buffer 0
    {
        const float4* src = (const float4*)wlf_s;
        ((float4*)wls[0])[threadIdx.x]       = src[threadIdx.x];
        ((float4*)wls[0])[256 + threadIdx.x] = src[256 + threadIdx.x];
    }
    __syncthreads();            // ps + tile 0 ready

    float4 plo = ps[row_lo];
    float4 phi = ps[row_hi];
    float qxl = M2C1 * plo.x, qyl = M2C1 * plo.y, qzl = M2C1 * plo.z, csl = plo.w;
    float qxh = M2C1 * phi.x, qyh = M2C1 * phi.y, qzh = M2C1 * phi.z, csh = phi.w;

    for (int tile = 0; tile < NTILES; tile++) {
        int cur = tile & 1;
        // issue next tile's global loads early (latency hidden by compute)
        float4 s0, s1;
        if (tile + 1 < NTILES) {
            const float4* src = (const float4*)(wlf_s + (tile + 1) * (JTILE * OW));
            s0 = src[threadIdx.x];
            s1 = src[256 + threadIdx.x];
        }

#pragma unroll
        for (int c = 0; c < CHUNKS; c++) {
            int j = tile * JTILE + c * 8 + (lane & 3);
            float4 pjl = ps[j];
            float4 pjh = ps[j + 4];

            float t00 = csl + pjl.w;
            t00 = fmaf(qxl, pjl.x, t00);
            t00 = fmaf(qyl, pjl.y, t00);
            t00 = fmaf(qzl, pjl.z, t00);
            float t10 = csh + pjl.w;
            t10 = fmaf(qxh, pjl.x, t10);
            t10 = fmaf(qyh, pjl.y, t10);
            t10 = fmaf(qzh, pjl.z, t10);
            float t01 = csl + pjh.w;
            t01 = fmaf(qxl, pjh.x, t01);
            t01 = fmaf(qyl, pjh.y, t01);
            t01 = fmaf(qzl, pjh.z, t01);
            float t11 = csh + pjh.w;
            t11 = fmaf(qxh, pjh.x, t11);
            t11 = fmaf(qyh, pjh.y, t11);
            t11 = fmaf(qzh, pjh.z, t11);

            unsigned a0 = cvt_tf32(ex2f(t00));
            unsigned a1 = cvt_tf32(ex2f(t10));
            unsigned a2 = cvt_tf32(ex2f(t01));
            unsigned a3 = cvt_tf32(ex2f(t11));

            const unsigned* bb = (const unsigned*)wls[cur] + c * 256;
#pragma unroll
            for (int nb = 0; nb < 4; nb++) {
                unsigned b0 = bb[(nb * 2 + 0) * 32 + lane];
                unsigned b1 = bb[(nb * 2 + 1) * 32 + lane];
                mma_tf32(acc + nb * 4, a0, a1, a2, a3, b0, b1);
            }
        }

        if (tile + 1 < NTILES) {
            ((float4*)wls[cur ^ 1])[threadIdx.x]       = s0;
            ((float4*)wls[cur ^ 1])[256 + threadIdx.x] = s1;
        }
        __syncthreads();
    }

    float invl = inv_d2[slice * NN + row_lo];
    float invh = inv_d2[slice * NN + row_hi];
    float* orow_lo = out + ((size_t)slice * NN + row_lo) * OW;
    float* orow_hi = out + ((size_t)slice * NN + row_hi) * OW;
#pragma unroll
    for (int nb = 0; nb < 4; nb++) {
        int col = nb * 8 + (lane & 3) * 2;
        float lb0 = __ldg(lin_b + col);
        float lb1 = __ldg(lin_b + col + 1);
        float2 vlo = make_float2(fmaf(acc[nb * 4 + 0], invl, lb0),
                                 fmaf(acc[nb * 4 + 1], invl, lb1));
        float2 vhi = make_float2(fmaf(acc[nb * 4 + 2], invh, lb0),
                                 fmaf(acc[nb * 4 + 3], invh, lb1));
        *(float2*)(orow_lo + col) = vlo;
        *(float2*)(orow_hi + col) = vhi;
    }
}

// ---------------------------------------------------------------------------
// Launcher
// ---------------------------------------------------------------------------
extern "C" void kernel_launch(void* const* d_in, const int* in_sizes, int n_in,
                              void* d_out, int out_size) {
    const float* positions = (const float*)d_in[0];
    const float* weights   = (const float*)d_in[1];
    const float* lin_w     = (const float*)d_in[2];
    const float* lin_b     = (const float*)d_in[3];
    float* out = (float*)d_out;

    int pos_elems = in_sizes[0];
    float* out_weights = out + pos_elems;

    float* inv_d2;
    float* wlf;
    cudaGetSymbolAddress((void**)&inv_d2, g_inv_d2);
    cudaGetSymbolAddress((void**)&wlf, g_wlf);

    cudaMemcpyAsync(out, positions, (size_t)pos_elems * sizeof(float),
                    cudaMemcpyDeviceToDevice);

    deg_kernel<<<NSLICE * 16, 256>>>(positions, inv_d2);
    wl_kernel<<<(NSLICE * NN) / 8, 256>>>(weights, lin_w, inv_d2, wlf);
    main_kernel<<<NSLICE * 16, 256>>>(positions, wlf, inv_d2, lin_b, out_weights);
}

// round 4
// speedup vs baseline: 2.6912x; 1.2420x over previous
#include <cuda_runtime.h>
#include <cstdint>

// Problem constants.
#define NSLICE 32      // B*KI = 8*4
#define NN     2048    // nodes per slice
#define IW     32
#define OW     32

// exp(-sq/2) = exp2(C1 * sq), C1 = -1/(2 ln 2)
#define C1   (-0.7213475204444817f)
#define M2C1 ( 1.4426950408889634f)   // -2*C1

// Scratch (device globals: allocation-free contract).
__device__ float g_inv_d2[NSLICE * NN];
// wl, tf32-rounded, B-fragment interleaved order:
// [slice][chunk(256)]{ [nb(4)][pos(32)][h(2)] } (256 floats per chunk)
__device__ float g_wlf[(size_t)NSLICE * NN * OW];

// ---------------------------------------------------------------------------
// PTX helpers
// ---------------------------------------------------------------------------
__device__ __forceinline__ float ex2f(float x) {
    float y; asm("ex2.approx.f32 %0, %1;" : "=f"(y) : "f"(x)); return y;
}
__device__ __forceinline__ unsigned cvt_tf32(float x) {
    unsigned y; asm("cvt.rna.tf32.f32 %0, %1;" : "=r"(y) : "f"(x)); return y;
}
// geometry MMA: C += A(16x4) * B(4x8), tf32
__device__ __forceinline__ void mma_k4(float& c0, float& c1, float& c2, float& c3,
                                       unsigned a0, unsigned a1, unsigned b0) {
    asm volatile(
        "mma.sync.aligned.m16n8k4.row.col.f32.tf32.tf32.f32 "
        "{%0,%1,%2,%3}, {%4,%5}, {%6}, {%0,%1,%2,%3};"
        : "+f"(c0), "+f"(c1), "+f"(c2), "+f"(c3)
        : "r"(a0), "r"(a1), "r"(b0));
}
// product MMA: C += A(16x8) * B(8x8), tf32
__device__ __forceinline__ void mma_k8(float* c, unsigned a0, unsigned a1,
                                       unsigned a2, unsigned a3,
                                       unsigned b0, unsigned b1) {
    asm volatile(
        "mma.sync.aligned.m16n8k8.row.col.f32.tf32.tf32.f32 "
        "{%0,%1,%2,%3}, {%4,%5,%6,%7}, {%8,%9}, {%0,%1,%2,%3};"
        : "+f"(c[0]), "+f"(c[1]), "+f"(c[2]), "+f"(c[3])
        : "r"(a0), "r"(a1), "r"(a2), "r"(a3), "r"(b0), "r"(b1));
}
__device__ __forceinline__ void cp_async16(uint32_t dst, const void* src) {
    asm volatile("cp.async.cg.shared.global [%0], [%1], 16;" :: "r"(dst), "l"(src));
}

// ---------------------------------------------------------------------------
// Per-slice geometry staging:
//  vg[chunk(256)][k(4)][n(8)]: tf32 coords, column-permuted (n -> j = (n>>1)+(n&1)*4)
//  csp[chunk(256)][tg(4)][2]:  C1*|p_j|^2, paired (j, j+4)
// ---------------------------------------------------------------------------
__device__ __forceinline__ void stage_slice(const float* __restrict__ p,
                                            float* vg, float* csp, int tid) {
    for (int n = tid; n < NN; n += 256) {
        float x = p[3 * n + 0], y = p[3 * n + 1], z = p[3 * n + 2];
        float s = x * x + y * y + z * z;
        int c = n >> 3, jn = n & 7;
        csp[c * 8 + (jn & 3) * 2 + (jn >> 2)] = C1 * s;
        int ncol = 2 * (jn & 3) + (jn >> 2);
        float* vgc = vg + c * 32;
        vgc[0 * 8 + ncol] = __uint_as_float(cvt_tf32(x));
        vgc[1 * 8 + ncol] = __uint_as_float(cvt_tf32(y));
        vgc[2 * 8 + ncol] = __uint_as_float(cvt_tf32(z));
        vgc[3 * 8 + ncol] = 0.0f;
    }
}

// per-thread row-side prep: returns cs_i, and A-frag component (tf32 of M2C1*coord[tg])
__device__ __forceinline__ void row_prep(const float* __restrict__ p, int row,
                                         int tg, float& cs, unsigned& ag) {
    float x = p[3 * row + 0], y = p[3 * row + 1], z = p[3 * row + 2];
    float s = x * x + y * y + z * z;
    cs = C1 * s;
    float comp = (tg == 0) ? x : (tg == 1) ? y : (tg == 2) ? z : 0.0f;
    ag = cvt_tf32(M2C1 * comp);
}

// ---------------------------------------------------------------------------
// Pass A: degrees. 512 blocks x 256 thr; warp owns 16 rows.
// ---------------------------------------------------------------------------
__global__ void __launch_bounds__(256) deg_kernel(
    const float* __restrict__ pos, float* __restrict__ inv_d2) {
    __shared__ float vg[256 * 32];   // 32 KB
    __shared__ float csp[NN];        // 8 KB

    int slice = blockIdx.x >> 4;
    int iblk  = blockIdx.x & 15;
    const float* p = pos + (size_t)slice * NN * 3;

    stage_slice(p, vg, csp, threadIdx.x);

    int warp = threadIdx.x >> 5;
    int lane = threadIdx.x & 31;
    int g = lane >> 2, tg = lane & 3;
    int row_lo = iblk * 128 + warp * 16 + g;
    int row_hi = row_lo + 8;

    float csl, csh; unsigned ag0, ag1;
    row_prep(p, row_lo, tg, csl, ag0);
    row_prep(p, row_hi, tg, csh, ag1);
    __syncthreads();

    float accl = 0.0f, acch = 0.0f;
#pragma unroll 4
    for (int c = 0; c < 256; c++) {
        unsigned bg = __float_as_uint(vg[c * 32 + tg * 8 + g]);
        float2 cj = *(const float2*)&csp[c * 8 + tg * 2];
        float t0 = csl + cj.x;   // (row_lo, j=c*8+tg)
        float t1 = csl + cj.y;   // (row_lo, j+4)
        float t2 = csh + cj.x;   // (row_hi, j)
        float t3 = csh + cj.y;   // (row_hi, j+4)
        mma_k4(t0, t1, t2, t3, ag0, ag1, bg);
        accl += ex2f(t0); accl += ex2f(t1);
        acch += ex2f(t2); acch += ex2f(t3);
    }
    accl += __shfl_xor_sync(0xffffffffu, accl, 1);
    accl += __shfl_xor_sync(0xffffffffu, accl, 2);
    acch += __shfl_xor_sync(0xffffffffu, acch, 1);
    acch += __shfl_xor_sync(0xffffffffu, acch, 2);
    if (tg == 0) {
        inv_d2[slice * NN + row_lo] = 1.0f / (accl * accl);
        inv_d2[slice * NN + row_hi] = 1.0f / (acch * acch);
    }
}

// ---------------------------------------------------------------------------
// Pass B: wl[j][o] = inv_d2[j] * (w[j,:] @ lin_w[o,:]); scatter into
// interleaved B-fragment order, tf32-rounded. One warp per node j.
// ---------------------------------------------------------------------------
__global__ void __launch_bounds__(256) wl_kernel(
    const float* __restrict__ w, const float* __restrict__ lin_w,
    const float* __restrict__ inv_d2, float* __restrict__ wlf) {
    __shared__ float lw[OW * 33];

    for (int t = threadIdx.x; t < OW * IW; t += 256)
        lw[(t >> 5) * 33 + (t & 31)] = lin_w[t];
    __syncthreads();

    int warp = threadIdx.x >> 5;
    int lane = threadIdx.x & 31;           // lane = output channel o
    long gj = (long)blockIdx.x * 8 + warp; // global node index

    float mw = w[gj * IW + lane];
    float acc = 0.0f;
#pragma unroll
    for (int k = 0; k < IW; k++) {
        float wv = __shfl_sync(0xffffffffu, mw, k);
        acc = fmaf(wv, lw[lane * 33 + k], acc);
    }
    acc *= inv_d2[gj];

    int slice = (int)(gj >> 11);
    int jl11  = (int)(gj & 2047);
    int chunk = jl11 >> 3;
    int h     = (jl11 >> 2) & 1;          // j half within chunk
    int jl    = jl11 & 3;
    int nb    = lane >> 3;
    int nl    = lane & 7;
    size_t addr = (((size_t)slice * 256 + chunk) * 256)
                + nb * 64 + (nl * 4 + jl) * 2 + h;
    wlf[addr] = __uint_as_float(cvt_tf32(acc));
}

// ---------------------------------------------------------------------------
// Pass C (hot): geometry-MMA + product-MMA mainloop, cp.async double buffer.
// dyn smem: vg (32KB) | csp (8KB) | wls[2] (16KB)
// ---------------------------------------------------------------------------
#define JTILE   64
#define NTILES  (NN / JTILE)

extern __shared__ float dsm[];

__global__ void __launch_bounds__(256) main_kernel(
    const float* __restrict__ pos, const float* __restrict__ wlf,
    const float* __restrict__ inv_d2, const float* __restrict__ lin_b,
    float* __restrict__ out) {
    float* vg  = dsm;            // 8192 floats
    float* csp = dsm + 8192;     // 2048 floats
    float* wls = dsm + 10240;    // 2 x 2048 floats

    int slice = blockIdx.x >> 4;
    int iblk  = blockIdx.x & 15;
    const float* p = pos + (size_t)slice * NN * 3;
    int tid = threadIdx.x;

    stage_slice(p, vg, csp, tid);

    int warp = tid >> 5;
    int lane = tid & 31;
    int g = lane >> 2, tg = lane & 3;
    int row_lo = iblk * 128 + warp * 16 + g;
    int row_hi = row_lo + 8;

    float csl, csh; unsigned ag0, ag1;
    row_prep(p, row_lo, tg, csl, ag0);
    row_prep(p, row_hi, tg, csh, ag1);

    const float* wsrc = wlf + (size_t)slice * NN * OW;
    uint32_t wls_sm = (uint32_t)__cvta_generic_to_shared(wls);

    // prologue: tile 0 -> buffer 0
    {
        const float4* src = (const float4*)wsrc;
        uint32_t d = wls_sm + tid * 16;
        cp_async16(d, src + tid);
        cp_async16(d + 4096, src + tid + 256);
        asm volatile("cp.async.commit_group;");
    }

    float acc[16];
#pragma unroll
    for (int r = 0; r < 16; r++) acc[r] = 0.0f;

    for (int tile = 0; tile < NTILES; tile++) {
        int cur = tile & 1;
        if (tile + 1 < NTILES) {
            const float4* src = (const float4*)(wsrc + (tile + 1) * (JTILE * OW));
            uint32_t d = wls_sm + (cur ^ 1) * 8192 + tid * 16;
            cp_async16(d, src + tid);
            cp_async16(d + 4096, src + tid + 256);
            asm volatile("cp.async.commit_group;");
            asm volatile("cp.async.wait_group 1;");
        } else {
            asm volatile("cp.async.wait_group 0;");
        }
        __syncthreads();   // tile data + (first iter) vg/csp visible

        const float* wbuf = wls + cur * 2048;
#pragma unroll
        for (int cc = 0; cc < JTILE / 8; cc++) {
            int c = tile * (JTILE / 8) + cc;
            unsigned bg = __float_as_uint(vg[c * 32 + tg * 8 + g]);
            float2 cj = *(const float2*)&csp[c * 8 + tg * 2];
            float t0 = csl + cj.x;
            float t1 = csl + cj.y;
            float t2 = csh + cj.x;
            float t3 = csh + cj.y;
            mma_k4(t0, t1, t2, t3, ag0, ag1, bg);

            unsigned a0 = cvt_tf32(ex2f(t0));   // (row_lo, k=tg)
            unsigned a1 = cvt_tf32(ex2f(t2));   // (row_hi, k=tg)
            unsigned a2 = cvt_tf32(ex2f(t1));   // (row_lo, k=tg+4)
            unsigned a3 = cvt_tf32(ex2f(t3));   // (row_hi, k=tg+4)

            const float* bbase = wbuf + cc * 256;
#pragma unroll
            for (int nb = 0; nb < 4; nb++) {
                uint2 b = *(const uint2*)(bbase + nb * 64 + lane * 2);
                mma_k8(acc + nb * 4, a0, a1, a2, a3, b.x, b.y);
            }
        }
        __syncthreads();   // all warps done with this buffer
    }

    float invl = inv_d2[slice * NN + row_lo];
    float invh = inv_d2[slice * NN + row_hi];
    float* orow_lo = out + ((size_t)slice * NN + row_lo) * OW;
    float* orow_hi = out + ((size_t)slice * NN + row_hi) * OW;
#pragma unroll
    for (int nb = 0; nb < 4; nb++) {
        int col = nb * 8 + tg * 2;
        float lb0 = __ldg(lin_b + col);
        float lb1 = __ldg(lin_b + col + 1);
        float2 vlo = make_float2(fmaf(acc[nb * 4 + 0], invl, lb0),
                                 fmaf(acc[nb * 4 + 1], invl, lb1));
        float2 vhi = make_float2(fmaf(acc[nb * 4 + 2], invh, lb0),
                                 fmaf(acc[nb * 4 + 3], invh, lb1));
        *(float2*)(orow_lo + col) = vlo;
        *(float2*)(orow_hi + col) = vhi;
    }
}

// ---------------------------------------------------------------------------
// Launcher
// ---------------------------------------------------------------------------
extern "C" void kernel_launch(void* const* d_in, const int* in_sizes, int n_in,
                              void* d_out, int out_size) {
    const float* positions = (const float*)d_in[0];
    const float* weights   = (const float*)d_in[1];
    const float* lin_w     = (const float*)d_in[2];
    const float* lin_b     = (const float*)d_in[3];
    float* out = (float*)d_out;

    int pos_elems = in_sizes[0];
    float* out_weights = out + pos_elems;

    float* inv_d2;
    float* wlf;
    cudaGetSymbolAddress((void**)&inv_d2, g_inv_d2);
    cudaGetSymbolAddress((void**)&wlf, g_wlf);

    static int smem_set = 0;
    if (!smem_set) {
        cudaFuncSetAttribute(main_kernel,
                             cudaFuncAttributeMaxDynamicSharedMemorySize, 57344);
        smem_set = 1;
    }

    cudaMemcpyAsync(out, positions, (size_t)pos_elems * sizeof(float),
                    cudaMemcpyDeviceToDevice);

    deg_kernel<<<NSLICE * 16, 256>>>(positions, inv_d2);
    wl_kernel<<<(NSLICE * NN) / 8, 256>>>(weights, lin_w, inv_d2, wlf);
    main_kernel<<<NSLICE * 16, 256, 57344>>>(positions, wlf, inv_d2, lin_b,
                                             out_weights);
}

// round 6
// speedup vs baseline: 3.0294x; 1.1257x over previous
#include <cuda_runtime.h>
#include <cstdint>

// Problem constants.
#define NSLICE 32      // B*KI = 8*4
#define NN     2048    // nodes per slice
#define IW     32
#define OW     32

// exp(-sq/2) = exp2(C1 * sq), C1 = -1/(2 ln 2)
#define C1   (-0.7213475204444817f)
#define M2C1 ( 1.4426950408889634f)   // -2*C1

// Scratch (device globals: allocation-free contract).
__device__ float g_inv_d2[NSLICE * NN];
// wl as packed bf16x2 in m16n8k16 B-fragment order:
// [slice][chunk16(128)][nb(4)][lane(32)][h(2)] -> uint32 = (lo=j even, hi=j odd)
__device__ unsigned g_wlb[(size_t)NSLICE * 128 * 4 * 64];

// ---------------------------------------------------------------------------
// PTX helpers
// ---------------------------------------------------------------------------
__device__ __forceinline__ float ex2f(float x) {
    float y; asm("ex2.approx.f32 %0, %1;" : "=f"(y) : "f"(x)); return y;
}
__device__ __forceinline__ unsigned cvt_tf32(float x) {
    unsigned y; asm("cvt.rna.tf32.f32 %0, %1;" : "=r"(y) : "f"(x)); return y;
}
__device__ __forceinline__ unsigned pack_bf16(float lo, float hi) {
    unsigned d;
    asm("cvt.rn.bf16x2.f32 %0, %1, %2;" : "=r"(d) : "f"(hi), "f"(lo));
    return d;
}
// geometry MMA: C += A(16x4) * B(4x8), tf32
__device__ __forceinline__ void mma_k4(float& c0, float& c1, float& c2, float& c3,
                                       unsigned a0, unsigned a1, unsigned b0) {
    asm volatile(
        "mma.sync.aligned.m16n8k4.row.col.f32.tf32.tf32.f32 "
        "{%0,%1,%2,%3}, {%4,%5}, {%6}, {%0,%1,%2,%3};"
        : "+f"(c0), "+f"(c1), "+f"(c2), "+f"(c3)
        : "r"(a0), "r"(a1), "r"(b0));
}
// product MMA: C += A(16x16) * B(16x8), bf16 -> fp32
__device__ __forceinline__ void mma_bf16(float* c, unsigned a0, unsigned a1,
                                         unsigned a2, unsigned a3,
                                         unsigned b0, unsigned b1) {
    asm volatile(
        "mma.sync.aligned.m16n8k16.row.col.f32.bf16.bf16.f32 "
        "{%0,%1,%2,%3}, {%4,%5,%6,%7}, {%8,%9}, {%0,%1,%2,%3};"
        : "+f"(c[0]), "+f"(c[1]), "+f"(c[2]), "+f"(c[3])
        : "r"(a0), "r"(a1), "r"(a2), "r"(a3), "r"(b0), "r"(b1));
}
__device__ __forceinline__ void cp_async16(uint32_t dst, const void* src) {
    asm volatile("cp.async.cg.shared.global [%0], [%1], 16;" :: "r"(dst), "l"(src));
}

// ---------------------------------------------------------------------------
// Pass A (fused): degrees (round-4 verified scheme: fp32 cs adds, tf32 dot
// product via k4 MMA), then wl epilogue in bf16 B-fragment order.
// 512 blocks x 256 thr; warp owns 16 rows.
// ---------------------------------------------------------------------------
__global__ void __launch_bounds__(256) deg_wl_kernel(
    const float* __restrict__ pos, const float* __restrict__ w,
    const float* __restrict__ lin_w, float* __restrict__ inv_d2,
    unsigned* __restrict__ wlb) {
    __shared__ float vg[256 * 32];   // 32 KB: [chunk8][k(4)][ncol(8)], k3 = 0
    __shared__ float csp[NN];        // 8 KB: [chunk8][tg(4)][2] = C1*|p|^2 pairs
    __shared__ float s_inv[128];
    __shared__ float lw[OW * 33];    // lin_w padded

    int slice = blockIdx.x >> 4;
    int iblk  = blockIdx.x & 15;
    const float* p = pos + (size_t)slice * NN * 3;
    int tid = threadIdx.x;

    for (int t = tid; t < OW * IW; t += 256)
        lw[(t >> 5) * 33 + (t & 31)] = lin_w[t];

    for (int n = tid; n < NN; n += 256) {
        float x = p[3 * n + 0], y = p[3 * n + 1], z = p[3 * n + 2];
        float s = x * x + y * y + z * z;
        int c = n >> 3, jn = n & 7;
        csp[c * 8 + (jn & 3) * 2 + (jn >> 2)] = C1 * s;
        int ncol = 2 * (jn & 3) + (jn >> 2);
        float* vgc = vg + c * 32;
        vgc[0 * 8 + ncol] = __uint_as_float(cvt_tf32(x));
        vgc[1 * 8 + ncol] = __uint_as_float(cvt_tf32(y));
        vgc[2 * 8 + ncol] = __uint_as_float(cvt_tf32(z));
        vgc[3 * 8 + ncol] = 0.0f;
    }

    int warp = tid >> 5;
    int lane = tid & 31;
    int g = lane >> 2, tg = lane & 3;
    int row_lo = iblk * 128 + warp * 16 + g;
    int row_hi = row_lo + 8;

    float csl, csh; unsigned ag0, ag1;
    {
        float x = p[3 * row_lo], y = p[3 * row_lo + 1], z = p[3 * row_lo + 2];
        csl = C1 * (x * x + y * y + z * z);
        float comp = (tg == 0) ? x : (tg == 1) ? y : (tg == 2) ? z : 0.0f;
        ag0 = cvt_tf32(M2C1 * comp);
        x = p[3 * row_hi]; y = p[3 * row_hi + 1]; z = p[3 * row_hi + 2];
        csh = C1 * (x * x + y * y + z * z);
        comp = (tg == 0) ? x : (tg == 1) ? y : (tg == 2) ? z : 0.0f;
        ag1 = cvt_tf32(M2C1 * comp);
    }
    __syncthreads();

    float a0l = 0.0f, a1l = 0.0f, a0h = 0.0f, a1h = 0.0f;
#pragma unroll 4
    for (int c = 0; c < 256; c++) {
        unsigned bg = __float_as_uint(vg[c * 32 + tg * 8 + g]);
        float2 cj = *(const float2*)&csp[c * 8 + tg * 2];
        float t0 = csl + cj.x;   // (row_lo, j=c*8+tg)
        float t1 = csl + cj.y;   // (row_lo, j+4)
        float t2 = csh + cj.x;   // (row_hi, j)
        float t3 = csh + cj.y;   // (row_hi, j+4)
        mma_k4(t0, t1, t2, t3, ag0, ag1, bg);
        a0l += ex2f(t0); a1l += ex2f(t1);
        a0h += ex2f(t2); a1h += ex2f(t3);
    }
    float accl = a0l + a1l;
    float acch = a0h + a1h;
    accl += __shfl_xor_sync(0xffffffffu, accl, 1);
    accl += __shfl_xor_sync(0xffffffffu, accl, 2);
    acch += __shfl_xor_sync(0xffffffffu, acch, 1);
    acch += __shfl_xor_sync(0xffffffffu, acch, 2);
    if (tg == 0) {
        float invl = 1.0f / (accl * accl);
        float invh = 1.0f / (acch * acch);
        s_inv[warp * 16 + g]     = invl;
        s_inv[warp * 16 + g + 8] = invh;
        inv_d2[slice * NN + row_lo] = invl;
        inv_d2[slice * NN + row_hi] = invh;
    }
    __syncthreads();

    // wl epilogue: this block's 128 nodes, two adjacent nodes per iteration,
    // packed into bf16x2 in B-fragment order for m16n8k16.
#pragma unroll 2
    for (int t = 0; t < 16; t += 2) {
        int nl  = warp * 16 + t;
        int j11 = iblk * 128 + nl;                 // even
        size_t gj = (size_t)slice * NN + j11;
        float wv0 = w[gj * IW + lane];
        float wv1 = w[(gj + 1) * IW + lane];
        float acc0 = 0.0f, acc1 = 0.0f;
#pragma unroll
        for (int k = 0; k < IW; k++) {
            float lwk = lw[lane * 33 + k];
            acc0 = fmaf(__shfl_sync(0xffffffffu, wv0, k), lwk, acc0);
            acc1 = fmaf(__shfl_sync(0xffffffffu, wv1, k), lwk, acc1);
        }
        acc0 *= s_inv[nl];
        acc1 *= s_inv[nl + 1];
        unsigned pk = pack_bf16(acc0, acc1);       // lo = even j

        int chunk16 = j11 >> 4;
        int kk      = j11 & 15;                    // even
        int tg_d    = (kk >> 1) & 3;
        int h       = kk >> 3;
        int nb_d    = lane >> 3;                   // o = lane
        int g_d     = lane & 7;
        size_t addr = (((size_t)slice * 128 + chunk16) * 4 + nb_d) * 64
                    + (g_d * 4 + tg_d) * 2 + h;
        wlb[addr] = pk;
    }
}

// ---------------------------------------------------------------------------
// Pass C (hot): fp32-FFMA distances + bf16 m16n8k16 product MMAs.
// smem: ps (32KB float4) | wls[2][1024] u32 (8KB). Double-buffered cp.async.
// ---------------------------------------------------------------------------
#define JTILE   64
#define NTILES  (NN / JTILE)

__global__ void __launch_bounds__(256) main_kernel(
    const float* __restrict__ pos, const unsigned* __restrict__ wlb,
    const float* __restrict__ inv_d2, const float* __restrict__ lin_b,
    float* __restrict__ out) {
    __shared__ float4   ps[NN];          // 32 KB
    __shared__ unsigned wls[2][1024];    // 2 x 4 KB

    int slice = blockIdx.x >> 4;
    int iblk  = blockIdx.x & 15;
    const float* p = pos + (size_t)slice * NN * 3;
    int tid = threadIdx.x;

    for (int n = tid; n < NN; n += 256) {
        float x = p[3 * n + 0], y = p[3 * n + 1], z = p[3 * n + 2];
        ps[n] = make_float4(x, y, z, C1 * (x * x + y * y + z * z));
    }

    int warp = tid >> 5;
    int lane = tid & 31;
    int g = lane >> 2, tg = lane & 3;
    int row_lo = iblk * 128 + warp * 16 + g;
    int row_hi = row_lo + 8;

    float qxl, qyl, qzl, csl, qxh, qyh, qzh, csh;
    {
        float x = p[3 * row_lo], y = p[3 * row_lo + 1], z = p[3 * row_lo + 2];
        csl = C1 * (x * x + y * y + z * z);
        qxl = M2C1 * x; qyl = M2C1 * y; qzl = M2C1 * z;
        x = p[3 * row_hi]; y = p[3 * row_hi + 1]; z = p[3 * row_hi + 2];
        csh = C1 * (x * x + y * y + z * z);
        qxh = M2C1 * x; qyh = M2C1 * y; qzh = M2C1 * z;
    }

    // wl source for this slice: 1024 u32 per 64-j tile
    const unsigned* wsrc = wlb + (size_t)slice * 32768;
    uint32_t wls_sm = (uint32_t)__cvta_generic_to_shared(&wls[0][0]);

    // prologue: tile 0 -> buffer 0 (256 thr x 16B = 4KB)
    cp_async16(wls_sm + tid * 16, (const uint4*)wsrc + tid);
    asm volatile("cp.async.commit_group;");

    float acc[16];
#pragma unroll
    for (int r = 0; r < 16; r++) acc[r] = 0.0f;

    for (int tile = 0; tile < NTILES; tile++) {
        int cur = tile & 1;
        if (tile + 1 < NTILES) {
            const uint4* src = (const uint4*)(wsrc + (tile + 1) * 1024);
            cp_async16(wls_sm + (cur ^ 1) * 4096 + tid * 16, src + tid);
            asm volatile("cp.async.commit_group;");
            asm volatile("cp.async.wait_group 1;");
        } else {
            asm volatile("cp.async.wait_group 0;");
        }
        __syncthreads();   // tile data + (first iter) ps visible

        const unsigned* wbuf = wls[cur];
#pragma unroll
        for (int cc = 0; cc < 4; cc++) {
            int jb = tile * JTILE + cc * 16;
            int j0 = jb + 2 * tg;       // k = 2tg
            float4 pj0 = ps[j0];
            float4 pj1 = ps[j0 + 1];    // k = 2tg+1
            float4 pj2 = ps[j0 + 8];    // k = 2tg+8
            float4 pj3 = ps[j0 + 9];    // k = 2tg+9

            float tl0 = csl + pj0.w;
            tl0 = fmaf(qxl, pj0.x, tl0); tl0 = fmaf(qyl, pj0.y, tl0); tl0 = fmaf(qzl, pj0.z, tl0);
            float tl1 = csl + pj1.w;
            tl1 = fmaf(qxl, pj1.x, tl1); tl1 = fmaf(qyl, pj1.y, tl1); tl1 = fmaf(qzl, pj1.z, tl1);
            float tl2 = csl + pj2.w;
            tl2 = fmaf(qxl, pj2.x, tl2); tl2 = fmaf(qyl, pj2.y, tl2); tl2 = fmaf(qzl, pj2.z, tl2);
            float tl3 = csl + pj3.w;
            tl3 = fmaf(qxl, pj3.x, tl3); tl3 = fmaf(qyl, pj3.y, tl3); tl3 = fmaf(qzl, pj3.z, tl3);

            float th0 = csh + pj0.w;
            th0 = fmaf(qxh, pj0.x, th0); th0 = fmaf(qyh, pj0.y, th0); th0 = fmaf(qzh, pj0.z, th0);
            float th1 = csh + pj1.w;
            th1 = fmaf(qxh, pj1.x, th1); th1 = fmaf(qyh, pj1.y, th1); th1 = fmaf(qzh, pj1.z, th1);
            float th2 = csh + pj2.w;
            th2 = fmaf(qxh, pj2.x, th2); th2 = fmaf(qyh, pj2.y, th2); th2 = fmaf(qzh, pj2.z, th2);
            float th3 = csh + pj3.w;
            th3 = fmaf(qxh, pj3.x, th3); th3 = fmaf(qyh, pj3.y, th3); th3 = fmaf(qzh, pj3.z, th3);

            unsigned a0 = pack_bf16(ex2f(tl0), ex2f(tl1));  // row_lo, k=2tg,2tg+1
            unsigned a1 = pack_bf16(ex2f(th0), ex2f(th1));  // row_hi
            unsigned a2 = pack_bf16(ex2f(tl2), ex2f(tl3));  // row_lo, k=+8
            unsigned a3 = pack_bf16(ex2f(th2), ex2f(th3));  // row_hi

#pragma unroll
            for (int nb = 0; nb < 4; nb++) {
                uint2 b = *(const uint2*)(wbuf + (cc * 4 + nb) * 64 + lane * 2);
                mma_bf16(acc + nb * 4, a0, a1, a2, a3, b.x, b.y);
            }
        }
        __syncthreads();   // all warps done with this buffer
    }

    float invl = inv_d2[slice * NN + row_lo];
    float invh = inv_d2[slice * NN + row_hi];
    float* orow_lo = out + ((size_t)slice * NN + row_lo) * OW;
    float* orow_hi = out + ((size_t)slice * NN + row_hi) * OW;
#pragma unroll
    for (int nb = 0; nb < 4; nb++) {
        int col = nb * 8 + tg * 2;
        float lb0 = __ldg(lin_b + col);
        float lb1 = __ldg(lin_b + col + 1);
        float2 vlo = make_float2(fmaf(acc[nb * 4 + 0], invl, lb0),
                                 fmaf(acc[nb * 4 + 1], invl, lb1));
        float2 vhi = make_float2(fmaf(acc[nb * 4 + 2], invh, lb0),
                                 fmaf(acc[nb * 4 + 3], invh, lb1));
        *(float2*)(orow_lo + col) = vlo;
        *(float2*)(orow_hi + col) = vhi;
    }
}

// ---------------------------------------------------------------------------
// Launcher
// ---------------------------------------------------------------------------
extern "C" void kernel_launch(void* const* d_in, const int* in_sizes, int n_in,
                              void* d_out, int out_size) {
    const float* positions = (const float*)d_in[0];
    const float* weights   = (const float*)d_in[1];
    const float* lin_w     = (const float*)d_in[2];
    const float* lin_b     = (const float*)d_in[3];
    float* out = (float*)d_out;

    int pos_elems = in_sizes[0];
    float* out_weights = out + pos_elems;

    float* inv_d2;
    unsigned* wlb;
    cudaGetSymbolAddress((void**)&inv_d2, g_inv_d2);
    cudaGetSymbolAddress((void**)&wlb, g_wlb);

    cudaMemcpyAsync(out, positions, (size_t)pos_elems * sizeof(float),
                    cudaMemcpyDeviceToDevice);

    deg_wl_kernel<<<NSLICE * 16, 256>>>(positions, weights, lin_w, inv_d2, wlb);
    main_kernel<<<NSLICE * 16, 256>>>(positions, wlb, inv_d2, lin_b, out_weights);
}

// round 7
// speedup vs baseline: 3.2270x; 1.0652x over previous
#include <cuda_runtime.h>
#include <cstdint>

// Problem constants.
#define NSLICE 32      // B*KI = 8*4
#define NN     2048    // nodes per slice
#define IW     32
#define OW     32

// exp(-sq/2) = exp2(C1 * sq), C1 = -1/(2 ln 2)
#define C1   (-0.7213475204444817f)
#define M2C1 ( 1.4426950408889634f)   // -2*C1
#define WLSCALE    4096.0f
#define INV_WLSCALE (1.0f / 4096.0f)

// Scratch (device globals: allocation-free contract).
__device__ float g_inv_d2[NSLICE * NN];
// wl as packed fp16x2 (scaled by WLSCALE) in m16n8k16 B-fragment order:
// [slice][chunk16(128)][nb(4)][lane(32)][h(2)] -> uint32 = (lo=j even, hi=j odd)
__device__ unsigned g_wlh[(size_t)NSLICE * 128 * 4 * 64];

// ---------------------------------------------------------------------------
// PTX helpers
// ---------------------------------------------------------------------------
__device__ __forceinline__ float ex2f(float x) {
    float y; asm("ex2.approx.f32 %0, %1;" : "=f"(y) : "f"(x)); return y;
}
__device__ __forceinline__ unsigned cvt_tf32(float x) {
    unsigned y; asm("cvt.rna.tf32.f32 %0, %1;" : "=r"(y) : "f"(x)); return y;
}
__device__ __forceinline__ unsigned pack_f16(float lo, float hi) {
    unsigned d;
    asm("cvt.rn.f16x2.f32 %0, %1, %2;" : "=r"(d) : "f"(hi), "f"(lo));
    return d;
}
// geometry MMA: C += A(16x4) * B(4x8), tf32
__device__ __forceinline__ void mma_k4(float& c0, float& c1, float& c2, float& c3,
                                       unsigned a0, unsigned a1, unsigned b0) {
    asm volatile(
        "mma.sync.aligned.m16n8k4.row.col.f32.tf32.tf32.f32 "
        "{%0,%1,%2,%3}, {%4,%5}, {%6}, {%0,%1,%2,%3};"
        : "+f"(c0), "+f"(c1), "+f"(c2), "+f"(c3)
        : "r"(a0), "r"(a1), "r"(b0));
}
// product MMA: C += A(16x16) * B(16x8), fp16 -> fp32
__device__ __forceinline__ void mma_f16(float* c, unsigned a0, unsigned a1,
                                        unsigned a2, unsigned a3,
                                        unsigned b0, unsigned b1) {
    asm volatile(
        "mma.sync.aligned.m16n8k16.row.col.f32.f16.f16.f32 "
        "{%0,%1,%2,%3}, {%4,%5,%6,%7}, {%8,%9}, {%0,%1,%2,%3};"
        : "+f"(c[0]), "+f"(c[1]), "+f"(c[2]), "+f"(c[3])
        : "r"(a0), "r"(a1), "r"(a2), "r"(a3), "r"(b0), "r"(b1));
}
__device__ __forceinline__ void cp_async16(uint32_t dst, const void* src) {
    asm volatile("cp.async.cg.shared.global [%0], [%1], 16;" :: "r"(dst), "l"(src));
}

// ---------------------------------------------------------------------------
// Pass A (fused): degrees (verified scheme: fp32 cs adds, tf32 dot product
// via k4 MMA), then wl epilogue in scaled-fp16 B-fragment order.
// 512 blocks x 256 thr; warp owns 16 rows.
// ---------------------------------------------------------------------------
__global__ void __launch_bounds__(256) deg_wl_kernel(
    const float* __restrict__ pos, const float* __restrict__ w,
    const float* __restrict__ lin_w, float* __restrict__ inv_d2,
    unsigned* __restrict__ wlh) {
    __shared__ float vg[256 * 32];   // 32 KB: [chunk8][k(4)][ncol(8)], k3 = 0
    __shared__ float csp[NN];        // 8 KB: [chunk8][tg(4)][2] = C1*|p|^2 pairs
    __shared__ float s_inv[128];
    __shared__ float lw[OW * 33];    // lin_w padded

    int slice = blockIdx.x >> 4;
    int iblk  = blockIdx.x & 15;
    const float* p = pos + (size_t)slice * NN * 3;
    int tid = threadIdx.x;

    for (int t = tid; t < OW * IW; t += 256)
        lw[(t >> 5) * 33 + (t & 31)] = lin_w[t];

    for (int n = tid; n < NN; n += 256) {
        float x = p[3 * n + 0], y = p[3 * n + 1], z = p[3 * n + 2];
        float s = x * x + y * y + z * z;
        int c = n >> 3, jn = n & 7;
        csp[c * 8 + (jn & 3) * 2 + (jn >> 2)] = C1 * s;
        int ncol = 2 * (jn & 3) + (jn >> 2);
        float* vgc = vg + c * 32;
        vgc[0 * 8 + ncol] = __uint_as_float(cvt_tf32(x));
        vgc[1 * 8 + ncol] = __uint_as_float(cvt_tf32(y));
        vgc[2 * 8 + ncol] = __uint_as_float(cvt_tf32(z));
        vgc[3 * 8 + ncol] = 0.0f;
    }

    int warp = tid >> 5;
    int lane = tid & 31;
    int g = lane >> 2, tg = lane & 3;
    int row_lo = iblk * 128 + warp * 16 + g;
    int row_hi = row_lo + 8;

    float csl, csh; unsigned ag0, ag1;
    {
        float x = p[3 * row_lo], y = p[3 * row_lo + 1], z = p[3 * row_lo + 2];
        csl = C1 * (x * x + y * y + z * z);
        float comp = (tg == 0) ? x : (tg == 1) ? y : (tg == 2) ? z : 0.0f;
        ag0 = cvt_tf32(M2C1 * comp);
        x = p[3 * row_hi]; y = p[3 * row_hi + 1]; z = p[3 * row_hi + 2];
        csh = C1 * (x * x + y * y + z * z);
        comp = (tg == 0) ? x : (tg == 1) ? y : (tg == 2) ? z : 0.0f;
        ag1 = cvt_tf32(M2C1 * comp);
    }
    __syncthreads();

    float a0l = 0.0f, a1l = 0.0f, a0h = 0.0f, a1h = 0.0f;
#pragma unroll 8
    for (int c = 0; c < 256; c++) {
        unsigned bg = __float_as_uint(vg[c * 32 + tg * 8 + g]);
        float2 cj = *(const float2*)&csp[c * 8 + tg * 2];
        float t0 = csl + cj.x;   // (row_lo, j=c*8+tg)
        float t1 = csl + cj.y;   // (row_lo, j+4)
        float t2 = csh + cj.x;   // (row_hi, j)
        float t3 = csh + cj.y;   // (row_hi, j+4)
        mma_k4(t0, t1, t2, t3, ag0, ag1, bg);
        a0l += ex2f(t0); a1l += ex2f(t1);
        a0h += ex2f(t2); a1h += ex2f(t3);
    }
    float accl = a0l + a1l;
    float acch = a0h + a1h;
    accl += __shfl_xor_sync(0xffffffffu, accl, 1);
    accl += __shfl_xor_sync(0xffffffffu, accl, 2);
    acch += __shfl_xor_sync(0xffffffffu, acch, 1);
    acch += __shfl_xor_sync(0xffffffffu, acch, 2);
    if (tg == 0) {
        float invl = 1.0f / (accl * accl);
        float invh = 1.0f / (acch * acch);
        s_inv[warp * 16 + g]     = invl;
        s_inv[warp * 16 + g + 8] = invh;
        inv_d2[slice * NN + row_lo] = invl;
        inv_d2[slice * NN + row_hi] = invh;
    }
    __syncthreads();

    // wl epilogue: this block's 128 nodes, two adjacent nodes per iteration,
    // packed into scaled fp16x2 in B-fragment order for m16n8k16.
#pragma unroll 2
    for (int t = 0; t < 16; t += 2) {
        int nl  = warp * 16 + t;
        int j11 = iblk * 128 + nl;                 // even
        size_t gj = (size_t)slice * NN + j11;
        float wv0 = w[gj * IW + lane];
        float wv1 = w[(gj + 1) * IW + lane];
        float acc0 = 0.0f, acc1 = 0.0f;
#pragma unroll
        for (int k = 0; k < IW; k++) {
            float lwk = lw[lane * 33 + k];
            acc0 = fmaf(__shfl_sync(0xffffffffu, wv0, k), lwk, acc0);
            acc1 = fmaf(__shfl_sync(0xffffffffu, wv1, k), lwk, acc1);
        }
        acc0 *= s_inv[nl] * WLSCALE;
        acc1 *= s_inv[nl + 1] * WLSCALE;
        unsigned pk = pack_f16(acc0, acc1);        // lo = even j

        int chunk16 = j11 >> 4;
        int kk      = j11 & 15;                    // even
        int tg_d    = (kk >> 1) & 3;
        int h       = kk >> 3;
        int nb_d    = lane >> 3;                   // o = lane
        int g_d     = lane & 7;
        size_t addr = (((size_t)slice * 128 + chunk16) * 4 + nb_d) * 64
                    + (g_d * 4 + tg_d) * 2 + h;
        wlh[addr] = pk;
    }
}

// ---------------------------------------------------------------------------
// Pass C (hot): fp32-FFMA distances + fp16 m16n8k16 product MMAs.
// smem: ps (32KB float4) | wls[2][2048] u32 (16KB) = 48KB -> 4 blocks/SM,
// all 512 blocks resident in one wave. Single __syncthreads per tile.
// ---------------------------------------------------------------------------
#define JTILE   128
#define NTILES  (NN / JTILE)

__global__ void __launch_bounds__(256) main_kernel(
    const float* __restrict__ pos, const unsigned* __restrict__ wlh,
    const float* __restrict__ inv_d2, const float* __restrict__ lin_b,
    float* __restrict__ out) {
    __shared__ float4   ps[NN];          // 32 KB
    __shared__ unsigned wls[2][2048];    // 2 x 8 KB

    int slice = blockIdx.x >> 4;
    int iblk  = blockIdx.x & 15;
    const float* p = pos + (size_t)slice * NN * 3;
    int tid = threadIdx.x;

    for (int n = tid; n < NN; n += 256) {
        float x = p[3 * n + 0], y = p[3 * n + 1], z = p[3 * n + 2];
        ps[n] = make_float4(x, y, z, C1 * (x * x + y * y + z * z));
    }

    int warp = tid >> 5;
    int lane = tid & 31;
    int g = lane >> 2, tg = lane & 3;
    int row_lo = iblk * 128 + warp * 16 + g;
    int row_hi = row_lo + 8;

    float qxl, qyl, qzl, csl, qxh, qyh, qzh, csh;
    {
        float x = p[3 * row_lo], y = p[3 * row_lo + 1], z = p[3 * row_lo + 2];
        csl = C1 * (x * x + y * y + z * z);
        qxl = M2C1 * x; qyl = M2C1 * y; qzl = M2C1 * z;
        x = p[3 * row_hi]; y = p[3 * row_hi + 1]; z = p[3 * row_hi + 2];
        csh = C1 * (x * x + y * y + z * z);
        qxh = M2C1 * x; qyh = M2C1 * y; qzh = M2C1 * z;
    }

    // wl source for this slice: 2048 u32 per 128-j tile
    const unsigned* wsrc = wlh + (size_t)slice * 32768;
    uint32_t wls_sm = (uint32_t)__cvta_generic_to_shared(&wls[0][0]);

    // prologue: tile 0 -> buffer 0 (256 thr x 2 x 16B = 8KB)
    {
        const uint4* src = (const uint4*)wsrc;
        cp_async16(wls_sm + tid * 16, src + tid);
        cp_async16(wls_sm + 4096 + tid * 16, src + tid + 256);
        asm volatile("cp.async.commit_group;");
    }

    float acc[16];
#pragma unroll
    for (int r = 0; r < 16; r++) acc[r] = 0.0f;

    for (int tile = 0; tile < NTILES; tile++) {
        int cur = tile & 1;
        asm volatile("cp.async.wait_group 0;");
        __syncthreads();   // buffer cur filled + everyone done with cur^1

        if (tile + 1 < NTILES) {
            const uint4* src = (const uint4*)(wsrc + (tile + 1) * 2048);
            uint32_t d = wls_sm + (cur ^ 1) * 8192 + tid * 16;
            cp_async16(d, src + tid);
            cp_async16(d + 4096, src + tid + 256);
            asm volatile("cp.async.commit_group;");
        }

        const unsigned* wbuf = wls[cur];
#pragma unroll
        for (int cc = 0; cc < JTILE / 16; cc++) {
            int jb = tile * JTILE + cc * 16;
            int j0 = jb + 2 * tg;       // k = 2tg
            float4 pj0 = ps[j0];
            float4 pj1 = ps[j0 + 1];    // k = 2tg+1
            float4 pj2 = ps[j0 + 8];    // k = 2tg+8
            float4 pj3 = ps[j0 + 9];    // k = 2tg+9

            float tl0 = csl + pj0.w;
            tl0 = fmaf(qxl, pj0.x, tl0); tl0 = fmaf(qyl, pj0.y, tl0); tl0 = fmaf(qzl, pj0.z, tl0);
            float tl1 = csl + pj1.w;
            tl1 = fmaf(qxl, pj1.x, tl1); tl1 = fmaf(qyl, pj1.y, tl1); tl1 = fmaf(qzl, pj1.z, tl1);
            float tl2 = csl + pj2.w;
            tl2 = fmaf(qxl, pj2.x, tl2); tl2 = fmaf(qyl, pj2.y, tl2); tl2 = fmaf(qzl, pj2.z, tl2);
            float tl3 = csl + pj3.w;
            tl3 = fmaf(qxl, pj3.x, tl3); tl3 = fmaf(qyl, pj3.y, tl3); tl3 = fmaf(qzl, pj3.z, tl3);

            float th0 = csh + pj0.w;
            th0 = fmaf(qxh, pj0.x, th0); th0 = fmaf(qyh, pj0.y, th0); th0 = fmaf(qzh, pj0.z, th0);
            float th1 = csh + pj1.w;
            th1 = fmaf(qxh, pj1.x, th1); th1 = fmaf(qyh, pj1.y, th1); th1 = fmaf(qzh, pj1.z, th1);
            float th2 = csh + pj2.w;
            th2 = fmaf(qxh, pj2.x, th2); th2 = fmaf(qyh, pj2.y, th2); th2 = fmaf(qzh, pj2.z, th2);
            float th3 = csh + pj3.w;
            th3 = fmaf(qxh, pj3.x, th3); th3 = fmaf(qyh, pj3.y, th3); th3 = fmaf(qzh, pj3.z, th3);

            unsigned a0 = pack_f16(ex2f(tl0), ex2f(tl1));  // row_lo, k=2tg,2tg+1
            unsigned a1 = pack_f16(ex2f(th0), ex2f(th1));  // row_hi
            unsigned a2 = pack_f16(ex2f(tl2), ex2f(tl3));  // row_lo, k=+8
            unsigned a3 = pack_f16(ex2f(th2), ex2f(th3));  // row_hi

#pragma unroll
            for (int nb = 0; nb < 4; nb++) {
                uint2 b = *(const uint2*)(wbuf + (cc * 4 + nb) * 64 + lane * 2);
                mma_f16(acc + nb * 4, a0, a1, a2, a3, b.x, b.y);
            }
        }
    }

    float invl = inv_d2[slice * NN + row_lo] * INV_WLSCALE;
    float invh = inv_d2[slice * NN + row_hi] * INV_WLSCALE;
    float* orow_lo = out + ((size_t)slice * NN + row_lo) * OW;
    float* orow_hi = out + ((size_t)slice * NN + row_hi) * OW;
#pragma unroll
    for (int nb = 0; nb < 4; nb++) {
        int col = nb * 8 + tg * 2;
        float lb0 = __ldg(lin_b + col);
        float lb1 = __ldg(lin_b + col + 1);
        float2 vlo = make_float2(fmaf(acc[nb * 4 + 0], invl, lb0),
                                 fmaf(acc[nb * 4 + 1], invl, lb1));
        float2 vhi = make_float2(fmaf(acc[nb * 4 + 2], invh, lb0),
                                 fmaf(acc[nb * 4 + 3], invh, lb1));
        *(float2*)(orow_lo + col) = vlo;
        *(float2*)(orow_hi + col) = vhi;
    }
}

// ---------------------------------------------------------------------------
// Launcher
// ---------------------------------------------------------------------------
extern "C" void kernel_launch(void* const* d_in, const int* in_sizes, int n_in,
                              void* d_out, int out_size) {
    const float* positions = (const float*)d_in[0];
    const float* weights   = (const float*)d_in[1];
    const float* lin_w     = (const float*)d_in[2];
    const float* lin_b     = (const float*)d_in[3];
    float* out = (float*)d_out;

    int pos_elems = in_sizes[0];
    float* out_weights = out + pos_elems;

    float* inv_d2;
    unsigned* wlh;
    cudaGetSymbolAddress((void**)&inv_d2, g_inv_d2);
    cudaGetSymbolAddress((void**)&wlh, g_wlh);

    cudaMemcpyAsync(out, positions, (size_t)pos_elems * sizeof(float),
                    cudaMemcpyDeviceToDevice);

    deg_wl_kernel<<<NSLICE * 16, 256>>>(positions, weights, lin_w, inv_d2, wlh);
    main_kernel<<<NSLICE * 16, 256>>>(positions, wlh, inv_d2, lin_b, out_weights);
}